// round 11
// baseline (speedup 1.0000x reference)
#include <cuda_runtime.h>

typedef unsigned long long ull;

#define T_STEPS 1024
#define BATCH   64
#define NCTA    128
#define NTHR    768

// v (K=1024 rows x 64 batch) read directly from global (L2-resident):
//   rows [0,256)    = x_t        (layer0 only)
//   rows [256,768)  = h0_{t-1}   (both layers)
//   rows [768,1024) = h1_{t-2}   (layer1 only)
// Warp split: 24 warps = 12 k-slices (ksl: 64 rows each) x 2 column-halves (ch).
//   L0: warp covers k in [64ksl, 64ksl+64), cols ch*8..ch*8+7
//   L1: local k1 in [64ksl, 64ksl+64), cols ch*4..ch*4+3
// Lane: pg = (lane>>1) (pairs 2pg,2pg+1); cl = lane&1 (quarter-split of cols).
// Per-lane accums: L0 4 cols x 2 pair-ulls + L1 2 cols x 2 = 12 ull (24 regs).
// Sequential L0 (ring-4 LDG prefetch) then L1 (ring-8) loops.
// 12 ksl-partials: one write wave -> one sum wave (2 syncs).

__device__ float g_xT[T_STEPS * 256 * BATCH];   // x transposed to [t][k][b]
__device__ float g_h0[2][512 * BATCH];
__device__ float g_h1[2][256 * BATCH];
__device__ unsigned g_count = 0;
__device__ volatile unsigned g_phase = 0;

__device__ __forceinline__ ull ffma2(ull a, ull b, ull c) {
    ull d;
    asm("fma.rn.f32x2 %0, %1, %2, %3;" : "=l"(d) : "l"(a), "l"(b), "l"(c));
    return d;
}
__device__ __forceinline__ ull addf2(ull a, ull b) {
    ull d;
    asm("add.rn.f32x2 %0, %1, %2;" : "=l"(d) : "l"(a), "l"(b));
    return d;
}
__device__ __forceinline__ ull dup32(float w) {
    unsigned u = __float_as_uint(w);
    return ((ull)u << 32) | (ull)u;
}
__device__ __forceinline__ float sigmf(float x) {
    return 1.0f / (1.0f + __expf(-x));
}

// Sense-reversing grid barrier. Safe: ~222KB smem -> 1 CTA/SM, 128 CTAs <= 148 SMs,
// all co-resident in wave 1. Count self-resets -> consistent across graph replays.
__device__ __forceinline__ void grid_barrier() {
    __syncthreads();
    if (threadIdx.x == 0) {
        __threadfence();
        unsigned ph = g_phase;
        if (atomicAdd(&g_count, 1u) == (unsigned)(gridDim.x - 1)) {
            atomicExch(&g_count, 0u);
            __threadfence();
            g_phase = ph + 1u;
        } else {
            while (g_phase == ph) { __nanosleep(32); }
            __threadfence();
        }
    }
    __syncthreads();
}

// 64-row L0 slice: 4 cols x 2 pair-ulls, ring-4 global prefetch.
// vsrc: ulonglong2 base (already + pg); row stride = 16 ulonglong2 (256B).
__device__ __forceinline__ void gemm64_L0(const ulonglong2* __restrict__ vsrc,
                                          const ull* __restrict__ wp,
                                          ull* __restrict__ a) {
    ulonglong2 rg[4];
    rg[0] = vsrc[0];
    rg[1] = vsrc[16];
    rg[2] = vsrc[32];
    rg[3] = vsrc[48];
#pragma unroll 4
    for (int r = 0; r < 60; r++) {
        ulonglong2 v = rg[r & 3];
        rg[r & 3] = vsrc[(r + 4) * 16];
        const ull* w = wp + r * 16;
        ulonglong2 w01 = *reinterpret_cast<const ulonglong2*>(w);
        ulonglong2 w23 = *reinterpret_cast<const ulonglong2*>(w + 2);
        a[0] = ffma2(w01.x, v.x, a[0]);  a[1] = ffma2(w01.x, v.y, a[1]);
        a[2] = ffma2(w01.y, v.x, a[2]);  a[3] = ffma2(w01.y, v.y, a[3]);
        a[4] = ffma2(w23.x, v.x, a[4]);  a[5] = ffma2(w23.x, v.y, a[5]);
        a[6] = ffma2(w23.y, v.x, a[6]);  a[7] = ffma2(w23.y, v.y, a[7]);
    }
#pragma unroll
    for (int r = 60; r < 64; r++) {
        ulonglong2 v = rg[r & 3];
        const ull* w = wp + r * 16;
        ulonglong2 w01 = *reinterpret_cast<const ulonglong2*>(w);
        ulonglong2 w23 = *reinterpret_cast<const ulonglong2*>(w + 2);
        a[0] = ffma2(w01.x, v.x, a[0]);  a[1] = ffma2(w01.x, v.y, a[1]);
        a[2] = ffma2(w01.y, v.x, a[2]);  a[3] = ffma2(w01.y, v.y, a[3]);
        a[4] = ffma2(w23.x, v.x, a[4]);  a[5] = ffma2(w23.x, v.y, a[5]);
        a[6] = ffma2(w23.y, v.x, a[6]);  a[7] = ffma2(w23.y, v.y, a[7]);
    }
}

// 64-row L1 slice: 2 cols x 2 pair-ulls, ring-8 global prefetch.
__device__ __forceinline__ void gemm64_L1(const ulonglong2* __restrict__ vsrc,
                                          const ull* __restrict__ wp,
                                          ull* __restrict__ a) {
    ulonglong2 rg[8];
#pragma unroll
    for (int i = 0; i < 8; i++) rg[i] = vsrc[i * 16];
#pragma unroll 8
    for (int r = 0; r < 56; r++) {
        ulonglong2 v = rg[r & 7];
        rg[r & 7] = vsrc[(r + 8) * 16];
        ulonglong2 w01 = *reinterpret_cast<const ulonglong2*>(wp + r * 8);
        a[0] = ffma2(w01.x, v.x, a[0]);  a[1] = ffma2(w01.x, v.y, a[1]);
        a[2] = ffma2(w01.y, v.x, a[2]);  a[3] = ffma2(w01.y, v.y, a[3]);
    }
#pragma unroll
    for (int r = 56; r < 64; r++) {
        ulonglong2 v = rg[r & 7];
        ulonglong2 w01 = *reinterpret_cast<const ulonglong2*>(wp + r * 8);
        a[0] = ffma2(w01.x, v.x, a[0]);  a[1] = ffma2(w01.x, v.y, a[1]);
        a[2] = ffma2(w01.y, v.x, a[2]);  a[3] = ffma2(w01.y, v.y, a[3]);
    }
}

__global__ void __launch_bounds__(NTHR, 1)
lstm2_kernel(const float* __restrict__ x,
             const float* __restrict__ Wih0, const float* __restrict__ bih0,
             const float* __restrict__ Whh0, const float* __restrict__ bhh0,
             const float* __restrict__ Wih1, const float* __restrict__ bih1,
             const float* __restrict__ Whh1, const float* __restrict__ bhh1,
             float* __restrict__ out)
{
    extern __shared__ char smraw[];
    ull*   w0d    = reinterpret_cast<ull*>(smraw);            // [768][16] lane-dup
    ull*   w1d    = w0d + 768 * 16;                           // [768][8]
    float* bcol   = reinterpret_cast<float*>(w1d + 768 * 8);  // [24] pad 32
    float* gates0 = bcol + 32;                                // [16][64]
    float* gates1 = gates0 + 16 * BATCH;                      // [8][64]
    ull*   red0   = reinterpret_cast<ull*>(gates1 + 8 * BATCH); // [16][12][32]
    ull*   red1   = red0 + 16 * 12 * 32;                      // [8][12][32]

    const int tid = threadIdx.x;
    const int cta = blockIdx.x;
    const int wrp = tid >> 5;            // 0..23
    const int ksl = wrp >> 1;            // 0..11: k rows [64ksl, 64ksl+64)
    const int ch  = wrp & 1;             // column half
    const int pg  = (tid & 31) >> 1;     // pair group 0..15
    const int cl  = tid & 1;             // column quarter

    // ---- one-time: transpose x (B,T,K) -> g_xT (T,K,B) ----
    {
        const size_t total = (size_t)BATCH * T_STEPS * 64;    // float4 groups
        for (size_t idx = (size_t)cta * NTHR + tid; idx < total; idx += (size_t)NCTA * NTHR) {
            int b  = (int)(idx & 63);
            size_t r = idx >> 6;
            int kg = (int)(r & 63);
            int t  = (int)(r >> 6);
            float4 v4 = *reinterpret_cast<const float4*>(
                x + ((size_t)b * T_STEPS + t) * 256 + kg * 4);
            float* dst = g_xT + ((size_t)t * 256 + kg * 4) * BATCH + b;
            dst[0 * BATCH] = v4.x;
            dst[1 * BATCH] = v4.y;
            dst[2 * BATCH] = v4.z;
            dst[3 * BATCH] = v4.w;
        }
    }

    // ---- one-time: stage weights into smem (lane-duplicated for f32x2) ----
    // L0 smem col cc = g*4 + u -> global j = g*512 + cta*4 + u
    for (int idx = tid; idx < 768 * 16; idx += NTHR) {
        int k = idx >> 4, cc = idx & 15;
        int g = cc >> 2, u = cc & 3;
        int j = g * 512 + cta * 4 + u;
        float w = (k < 256) ? Wih0[(size_t)k * 2048 + j]
                            : Whh0[(size_t)(k - 256) * 2048 + j];
        w0d[idx] = dup32(w);
    }
    // L1 smem col cc = g*2 + u1 -> global j = g*256 + cta*2 + u1
    for (int idx = tid; idx < 768 * 8; idx += NTHR) {
        int k = idx >> 3, cc = idx & 7;
        int g = cc >> 1, u1 = cc & 1;
        int j = g * 256 + cta * 2 + u1;
        float w = (k < 512) ? Wih1[(size_t)k * 1024 + j]
                            : Whh1[(size_t)(k - 512) * 1024 + j];
        w1d[idx] = dup32(w);
    }
    if (tid < 16) {
        int g = tid >> 2, u = tid & 3;
        int j = g * 512 + cta * 4 + u;
        bcol[tid] = bih0[j] + bhh0[j];
    } else if (tid < 24) {
        int cc = tid - 16, g = cc >> 1, u1 = cc & 1;
        int j = g * 256 + cta * 2 + u1;
        bcol[tid] = bih1[j] + bhh1[j];
    }

    float cst = 0.0f;   // c0 for tid<256 (unit tid>>6, batch tid&63); c1 for [256,384)

    __syncthreads();
    grid_barrier();     // g_xT complete

    // ---- main recurrence: iteration t = layer0 step t + layer1 step t-1 ----
    for (int t = 0; t <= T_STEPS; t++) {
        const bool hasL0 = (t < T_STEPS);
        const bool hasL1 = (t >= 1);

        ull a0[8], a1[4];
#pragma unroll
        for (int j = 0; j < 8; j++) a0[j] = 0ull;
#pragma unroll
        for (int j = 0; j < 4; j++) a1[j] = 0ull;

        // L0: ksl<4 -> x_t rows; ksl>=4 -> h0_{t-1} rows (zero at t=0)
        const bool d0 = hasL0 && (ksl < 4 || t >= 1);
        // L1: ksl<8 -> h0_{t-1}; ksl>=8 -> h1_{t-2} (zero until t>=2)
        const bool d1 = hasL1 && (ksl < 8 || t >= 2);

        if (d0) {
            const float* s0 = (ksl < 4)
                ? (g_xT + (size_t)t * 16384 + ksl * 4096)
                : (g_h0[(t - 1) & 1] + (ksl - 4) * 4096);
            gemm64_L0(reinterpret_cast<const ulonglong2*>(s0) + pg,
                      w0d + (size_t)(64 * ksl) * 16 + ch * 8 + cl * 4, a0);
        }
        if (d1) {
            const float* s1 = (ksl < 8)
                ? (g_h0[(t - 1) & 1] + ksl * 4096)
                : (g_h1[t & 1] + (ksl - 8) * 4096);
            gemm64_L1(reinterpret_cast<const ulonglong2*>(s1) + pg,
                      w1d + (size_t)(64 * ksl) * 8 + ch * 4 + cl * 2, a1);
        }

        // ---- one write wave: partials into slot ksl ----
        {
            const int c0 = ch * 8 + cl * 4;
            const int c1 = ch * 4 + cl * 2;
#pragma unroll
            for (int j = 0; j < 4; j++)
                *reinterpret_cast<ulonglong2*>(
                    red0 + ((c0 + j) * 12 + ksl) * 32 + 2 * pg) =
                    make_ulonglong2(a0[2 * j], a0[2 * j + 1]);
#pragma unroll
            for (int j = 0; j < 2; j++)
                *reinterpret_cast<ulonglong2*>(
                    red1 + ((c1 + j) * 12 + ksl) * 32 + 2 * pg) =
                    make_ulonglong2(a1[2 * j], a1[2 * j + 1]);
        }
        __syncthreads();

        // ---- final: sum 12 slots + bias -> gates (one ull per thread) ----
        if (tid < 512) {
            int cc = tid >> 5, pr = tid & 31;
            const ull* r = red0 + (cc * 12) * 32 + pr;
            ull s = dup32(bcol[cc]);
#pragma unroll
            for (int w = 0; w < 12; w++) s = addf2(s, r[w * 32]);
            *reinterpret_cast<ull*>(&gates0[cc * 64 + 2 * pr]) = s;
        } else {
            int i = tid - 512, cc = i >> 5, pr = i & 31;
            const ull* r = red1 + (cc * 12) * 32 + pr;
            ull s = dup32(bcol[16 + cc]);
#pragma unroll
            for (int w = 0; w < 12; w++) s = addf2(s, r[w * 32]);
            *reinterpret_cast<ull*>(&gates1[cc * 64 + 2 * pr]) = s;
        }
        __syncthreads();

        // ---- activations (disjoint warps) ----
        if (hasL0 && tid < 256) {
            int u = tid >> 6, b = tid & 63;
            float gi = gates0[(0 * 4 + u) * 64 + b];
            float gf = gates0[(1 * 4 + u) * 64 + b];
            float gg = gates0[(2 * 4 + u) * 64 + b];
            float go = gates0[(3 * 4 + u) * 64 + b];
            cst = sigmf(gf) * cst + sigmf(gi) * tanhf(gg);
            g_h0[t & 1][(cta * 4 + u) * 64 + b] = sigmf(go) * tanhf(cst);
        }
        if (hasL1 && tid >= 256 && tid < 384) {
            int u1 = (tid >> 6) & 1, b = tid & 63;
            float gi = gates1[(0 * 2 + u1) * 64 + b];
            float gf = gates1[(1 * 2 + u1) * 64 + b];
            float gg = gates1[(2 * 2 + u1) * 64 + b];
            float go = gates1[(3 * 2 + u1) * 64 + b];
            cst = sigmf(gf) * cst + sigmf(gi) * tanhf(gg);
            float h = sigmf(go) * tanhf(cst);
            int s = t - 1;
            g_h1[s & 1][(cta * 2 + u1) * 64 + b] = h;
            out[((size_t)b * T_STEPS + s) * 256 + cta * 2 + u1] = h;
        }

        if (t < T_STEPS) grid_barrier();
    }
}

// smem: w0d 98304 + w1d 49152 + bcol 128 + gates 6144 + red0 49152 + red1 24576 = 227456
#define SMEM_BYTES (98304 + 49152 + 128 + 4096 + 2048 + 49152 + 24576)

extern "C" void kernel_launch(void* const* d_in, const int* in_sizes, int n_in,
                              void* d_out, int out_size) {
    (void)in_sizes; (void)n_in; (void)out_size;
    cudaFuncSetAttribute(lstm2_kernel,
                         cudaFuncAttributeMaxDynamicSharedMemorySize, SMEM_BYTES);
    lstm2_kernel<<<NCTA, NTHR, SMEM_BYTES>>>(
        (const float*)d_in[0],
        (const float*)d_in[1], (const float*)d_in[2],
        (const float*)d_in[3], (const float*)d_in[4],
        (const float*)d_in[5], (const float*)d_in[6],
        (const float*)d_in[7], (const float*)d_in[8],
        (float*)d_out);
}